// round 3
// baseline (speedup 1.0000x reference)
#include <cuda_runtime.h>
#include <cuda_bf16.h>
#include <cstdint>

// INGP hash-grid encoder, round 2 (resubmit): persistent blocks stage the 5
// coarse-level sub-tables (x in [0,1) => footprint [floor(res/2), res]^3) into
// shared memory. 32 warps = 16 levels x 2 sub-warps (level-pure, no divergence).
// Output via stride-17 smem transpose buffer => fully coalesced STG.

#define NLEV 16
#define LOG2T 19
#define TSIZE (1u << LOG2T)
#define TMASK (TSIZE - 1u)

#define TBL_N 27293              // 729+1331+2744+4913+17576 float2 entries
#define TILE_PTS 64
#define NTHREADS 1024

__constant__ float c_res[NLEV] = {
    16.f, 20.f, 25.f, 32.f, 40.f, 50.f, 64.f, 80.f,
    101.f, 128.f, 161.f, 203.f, 256.f, 322.f, 406.f, 512.f
};
// staged-level metadata: base coord, dim (0 if not staged), float2 offset
__constant__ int c_sbase[NLEV] = { 8, 10, 12, 16, -1, 25, -1,-1,-1,-1,-1,-1,-1,-1,-1,-1 };
__constant__ int c_sdim [NLEV] = { 9, 11, 14, 17,  0, 26,  0, 0, 0, 0, 0, 0, 0, 0, 0, 0 };
__constant__ int c_soff [NLEV] = { 0, 729, 2060, 4804, 0, 9717, 0,0,0,0,0,0,0,0,0,0 };
__constant__ int c_fill [5]    = { 0, 1, 2, 3, 5 };

struct Smem {
    float2 tbl[TBL_N];          // 218,344 B
    float  xs[TILE_PTS * 3];    // 768 B
    float  bufx[TILE_PTS * 17]; // 4,352 B (stride 17 => conflict-free)
    float  bufy[TILE_PTS * 17]; // 4,352 B
};                              // total 227,816 B (< 232,448 B limit)

__device__ __forceinline__ void gather_global(
    const float2* __restrict__ tbl,
    unsigned hx0, unsigned hx1, unsigned hy0, unsigned hy1,
    unsigned hz0, unsigned hz1,
    float2& e0, float2& e1, float2& e2, float2& e3,
    float2& e4, float2& e5, float2& e6, float2& e7)
{
    unsigned i0 = (hx0 ^ hy0 ^ hz0) & TMASK;
    unsigned i1 = (hx0 ^ hy0 ^ hz1) & TMASK;
    unsigned i2 = (hx0 ^ hy1 ^ hz0) & TMASK;
    unsigned i3 = (hx0 ^ hy1 ^ hz1) & TMASK;
    unsigned i4 = (hx1 ^ hy0 ^ hz0) & TMASK;
    unsigned i5 = (hx1 ^ hy0 ^ hz1) & TMASK;
    unsigned i6 = (hx1 ^ hy1 ^ hz0) & TMASK;
    unsigned i7 = (hx1 ^ hy1 ^ hz1) & TMASK;
    e0 = __ldg(tbl + i0);  e1 = __ldg(tbl + i1);
    e2 = __ldg(tbl + i2);  e3 = __ldg(tbl + i3);
    e4 = __ldg(tbl + i4);  e5 = __ldg(tbl + i5);
    e6 = __ldg(tbl + i6);  e7 = __ldg(tbl + i7);
}

__global__ __launch_bounds__(NTHREADS, 1) void ingp_hash_kernel(
    const float*  __restrict__ x,      // (N,3)
    const float2* __restrict__ emb,    // (16, 2^19) float2
    float2*       __restrict__ out2,   // (N,16) float2
    int npts, int pts_per_blk)
{
    extern __shared__ Smem sm[];
    Smem& s = sm[0];

    int tid = threadIdx.x;

    // ---------------- fill staged tables (once per block) ----------------
    #pragma unroll
    for (int si = 0; si < 5; si++) {
        int lv  = c_fill[si];
        int d   = c_sdim[lv];
        int n   = d * d * d;
        int off = c_soff[lv];
        int b   = c_sbase[lv];
        const float2* __restrict__ g = emb + (size_t)lv * TSIZE;
        for (int i = tid; i < n; i += NTHREADS) {
            int kk = i % d;
            int t  = i / d;
            int jj = t % d;
            int ii = t / d;
            unsigned cx = (unsigned)(b + ii);
            unsigned cy = (unsigned)(b + jj);
            unsigned cz = (unsigned)(b + kk);
            unsigned h = (cx ^ (cy * 2654435761u) ^ (cz * 805459861u)) & TMASK;
            s.tbl[off + i] = __ldg(g + h);
        }
    }
    __syncthreads();

    // ---------------- per-block point range ----------------
    int p0   = blockIdx.x * pts_per_blk;
    int pend = min(p0 + pts_per_blk, npts);

    int wid  = tid >> 5;
    int lane = tid & 31;
    int L    = wid >> 1;                  // level for this warp
    int psub = ((wid & 1) << 5) + lane;   // 0..63 point slot in tile

    float res  = c_res[L];
    float grid = 2.0f / res;
    int sb = c_sbase[L], sd = c_sdim[L], soff = c_soff[L];
    const float2* __restrict__ gtbl = emb + (size_t)L * TSIZE;

    for (int base_p = p0; base_p < pend; base_p += TILE_PTS) {
        // stage x for this tile
        if (tid < TILE_PTS * 3) {
            int gi = base_p * 3 + tid;
            s.xs[tid] = (base_p + (tid / 3) < pend) ? x[gi] : 0.0f;
        }
        __syncthreads();

        int p = base_p + psub;
        if (p < pend) {
            float px = s.xs[psub * 3 + 0];
            float py = s.xs[psub * 3 + 1];
            float pz = s.xs[psub * 3 + 2];
            px = fminf(fmaxf(px, -1.0f), 1.0f);
            py = fminf(fmaxf(py, -1.0f), 1.0f);
            pz = fminf(fmaxf(pz, -1.0f), 1.0f);

            int bx = __float2int_rd((px + 1.0f) / grid);
            int by = __float2int_rd((py + 1.0f) / grid);
            int bz = __float2int_rd((pz + 1.0f) / grid);

            float wx = (px - ((float)bx * grid - 1.0f)) / grid;
            float wy = (py - ((float)by * grid - 1.0f)) / grid;
            float wz = (pz - ((float)bz * grid - 1.0f)) / grid;

            float2 e0, e1, e2, e3, e4, e5, e6, e7;

            if (sd > 0) {
                int lx = bx - sb, ly = by - sb, lz = bz - sb;
                unsigned dm1 = (unsigned)(sd - 1);
                if ((unsigned)lx < dm1 && (unsigned)ly < dm1 && (unsigned)lz < dm1) {
                    int i000 = soff + (lx * sd + ly) * sd + lz;
                    int i100 = i000 + sd * sd;
                    e0 = s.tbl[i000];          e1 = s.tbl[i000 + 1];
                    e2 = s.tbl[i000 + sd];     e3 = s.tbl[i000 + sd + 1];
                    e4 = s.tbl[i100];          e5 = s.tbl[i100 + 1];
                    e6 = s.tbl[i100 + sd];     e7 = s.tbl[i100 + sd + 1];
                } else {
                    // fallback (never taken for x in [0,1))
                    unsigned hx0 = (unsigned)bx,       hx1 = (unsigned)(bx + 1);
                    unsigned hy0 = (unsigned)by * 2654435761u;
                    unsigned hy1 = (unsigned)(by + 1) * 2654435761u;
                    unsigned hz0 = (unsigned)bz * 805459861u;
                    unsigned hz1 = (unsigned)(bz + 1) * 805459861u;
                    gather_global(gtbl, hx0, hx1, hy0, hy1, hz0, hz1,
                                  e0, e1, e2, e3, e4, e5, e6, e7);
                }
            } else {
                unsigned hx0 = (unsigned)bx,       hx1 = (unsigned)(bx + 1);
                unsigned hy0 = (unsigned)by * 2654435761u;
                unsigned hy1 = (unsigned)(by + 1) * 2654435761u;
                unsigned hz0 = (unsigned)bz * 805459861u;
                unsigned hz1 = (unsigned)(bz + 1) * 805459861u;
                gather_global(gtbl, hx0, hx1, hy0, hy1, hz0, hz1,
                              e0, e1, e2, e3, e4, e5, e6, e7);
            }

            float ox = 1.0f - wx, oy = 1.0f - wy, oz = 1.0f - wz;
            float w0 = ox * oy * oz;
            float w1 = ox * oy * wz;
            float w2 = ox * wy * oz;
            float w3 = ox * wy * wz;
            float w4 = wx * oy * oz;
            float w5 = wx * oy * wz;
            float w6 = wx * wy * oz;
            float w7 = wx * wy * wz;

            float f0 = w0 * e0.x;
            float f1 = w0 * e0.y;
            f0 = fmaf(w1, e1.x, f0);  f1 = fmaf(w1, e1.y, f1);
            f0 = fmaf(w2, e2.x, f0);  f1 = fmaf(w2, e2.y, f1);
            f0 = fmaf(w3, e3.x, f0);  f1 = fmaf(w3, e3.y, f1);
            f0 = fmaf(w4, e4.x, f0);  f1 = fmaf(w4, e4.y, f1);
            f0 = fmaf(w5, e5.x, f0);  f1 = fmaf(w5, e5.y, f1);
            f0 = fmaf(w6, e6.x, f0);  f1 = fmaf(w6, e6.y, f1);
            f0 = fmaf(w7, e7.x, f0);  f1 = fmaf(w7, e7.y, f1);

            s.bufx[psub * 17 + L] = f0;
            s.bufy[psub * 17 + L] = f1;
        }
        __syncthreads();

        // coalesced flush: thread t -> point (t>>4), level (t&15)
        int pp = tid >> 4;
        int ll = tid & 15;
        int gp = base_p + pp;
        if (gp < pend) {
            out2[(size_t)gp * NLEV + ll] =
                make_float2(s.bufx[pp * 17 + ll], s.bufy[pp * 17 + ll]);
        }
        // safe: next-iter xs writes are disjoint from buf; buf rewritten only
        // after the next tile's first __syncthreads.
    }
}

extern "C" void kernel_launch(void* const* d_in, const int* in_sizes, int n_in,
                              void* d_out, int out_size)
{
    const float*  x   = (const float*)d_in[0];
    const float2* emb = (const float2*)d_in[1];
    float2*       out = (float2*)d_out;

    int npts = in_sizes[0] / 3;

    int nsm = 0;
    if (cudaDeviceGetAttribute(&nsm, cudaDevAttrMultiProcessorCount, 0) != cudaSuccess
        || nsm <= 0) {
        nsm = 148;
    }
    int grid = nsm;
    int ppb = (npts + grid - 1) / grid;

    size_t smem_bytes = sizeof(Smem);
    cudaFuncSetAttribute(ingp_hash_kernel,
                         cudaFuncAttributeMaxDynamicSharedMemorySize,
                         (int)smem_bytes);

    ingp_hash_kernel<<<grid, NTHREADS, smem_bytes>>>(x, emb, out, npts, ppb);
}

// round 5
// speedup vs baseline: 1.3449x; 1.3449x over previous
#include <cuda_runtime.h>
#include <cuda_bf16.h>
#include <cstdint>

// INGP hash-grid encoder, round 4: R1's barrier-free structure (one thread per
// (point,level), grid-stride, coalesced stores) + one-time smem staging of the
// 5 coarse-level sub-tables (x in [0,1) => footprint [floor(res/2), res]^3).
// Steady state has ZERO barriers; staged lanes use LDS, others LDG.

#define NLEV 16
#define LOG2T 19
#define TSIZE (1u << LOG2T)
#define TMASK (TSIZE - 1u)

#define TBL_N 27293              // 729+1331+2744+4913+17576 float2 entries
#define NTHREADS 1024

__constant__ float c_res[NLEV] = {
    16.f, 20.f, 25.f, 32.f, 40.f, 50.f, 64.f, 80.f,
    101.f, 128.f, 161.f, 203.f, 256.f, 322.f, 406.f, 512.f
};
// staged-level metadata: base coord, dim (0 if not staged), float2 offset
__constant__ int c_sbase[NLEV] = { 8, 10, 12, 16, -1, 25, -1,-1,-1,-1,-1,-1,-1,-1,-1,-1 };
__constant__ int c_sdim [NLEV] = { 9, 11, 14, 17,  0, 26,  0, 0, 0, 0, 0, 0, 0, 0, 0, 0 };
__constant__ int c_soff [NLEV] = { 0, 729, 2060, 4804, 0, 9717, 0,0,0,0,0,0,0,0,0,0 };
__constant__ int c_fill [5]    = { 0, 1, 2, 3, 5 };

__device__ __forceinline__ void gather_global(
    const float2* __restrict__ tbl,
    unsigned hx0, unsigned hx1, unsigned hy0, unsigned hy1,
    unsigned hz0, unsigned hz1,
    float2& e0, float2& e1, float2& e2, float2& e3,
    float2& e4, float2& e5, float2& e6, float2& e7)
{
    unsigned i0 = (hx0 ^ hy0 ^ hz0) & TMASK;
    unsigned i1 = (hx0 ^ hy0 ^ hz1) & TMASK;
    unsigned i2 = (hx0 ^ hy1 ^ hz0) & TMASK;
    unsigned i3 = (hx0 ^ hy1 ^ hz1) & TMASK;
    unsigned i4 = (hx1 ^ hy0 ^ hz0) & TMASK;
    unsigned i5 = (hx1 ^ hy0 ^ hz1) & TMASK;
    unsigned i6 = (hx1 ^ hy1 ^ hz0) & TMASK;
    unsigned i7 = (hx1 ^ hy1 ^ hz1) & TMASK;
    e0 = __ldg(tbl + i0);  e1 = __ldg(tbl + i1);
    e2 = __ldg(tbl + i2);  e3 = __ldg(tbl + i3);
    e4 = __ldg(tbl + i4);  e5 = __ldg(tbl + i5);
    e6 = __ldg(tbl + i6);  e7 = __ldg(tbl + i7);
}

__global__ __launch_bounds__(NTHREADS, 1) void ingp_hash_kernel(
    const float*  __restrict__ x,      // (N,3)
    const float2* __restrict__ emb,    // (16, 2^19) float2
    float2*       __restrict__ out2,   // (N,16) float2
    int npts)
{
    extern __shared__ float2 s_tbl[];   // TBL_N entries, 218,344 B

    int tid = threadIdx.x;

    // ---------------- fill staged tables (once per block) ----------------
    #pragma unroll
    for (int si = 0; si < 5; si++) {
        int lv  = c_fill[si];
        int d   = c_sdim[lv];
        int n   = d * d * d;
        int off = c_soff[lv];
        int b   = c_sbase[lv];
        const float2* __restrict__ g = emb + (size_t)lv * TSIZE;
        for (int i = tid; i < n; i += NTHREADS) {
            int kk = i % d;
            int t  = i / d;
            int jj = t % d;
            int ii = t / d;
            unsigned cx = (unsigned)(b + ii);
            unsigned cy = (unsigned)(b + jj);
            unsigned cz = (unsigned)(b + kk);
            unsigned h = (cx ^ (cy * 2654435761u) ^ (cz * 805459861u)) & TMASK;
            s_tbl[off + i] = __ldg(g + h);
        }
    }
    __syncthreads();   // the ONLY barrier in the kernel

    // ---------------- barrier-free grid-stride main loop ----------------
    // stride is a multiple of 16 => this thread's level is loop-invariant.
    long long total  = (long long)npts * NLEV;
    long long stride = (long long)gridDim.x * NTHREADS;
    long long w0i    = (long long)blockIdx.x * NTHREADS + tid;

    int   l    = (int)(w0i & 15);
    float res  = c_res[l];
    float grid = 2.0f / res;
    int sb = c_sbase[l], sd = c_sdim[l], soff = c_soff[l];
    bool staged = (sd > 0);
    const float2* __restrict__ gtbl = emb + (size_t)l * TSIZE;

    for (long long w = w0i; w < total; w += stride) {
        int p = (int)(w >> 4);

        float px = __ldg(x + 3 * p + 0);
        float py = __ldg(x + 3 * p + 1);
        float pz = __ldg(x + 3 * p + 2);
        px = fminf(fmaxf(px, -1.0f), 1.0f);
        py = fminf(fmaxf(py, -1.0f), 1.0f);
        pz = fminf(fmaxf(pz, -1.0f), 1.0f);

        int bx = __float2int_rd((px + 1.0f) / grid);
        int by = __float2int_rd((py + 1.0f) / grid);
        int bz = __float2int_rd((pz + 1.0f) / grid);

        float wx = (px - ((float)bx * grid - 1.0f)) / grid;
        float wy = (py - ((float)by * grid - 1.0f)) / grid;
        float wz = (pz - ((float)bz * grid - 1.0f)) / grid;

        float2 e0, e1, e2, e3, e4, e5, e6, e7;

        int lx = bx - sb, ly = by - sb, lz = bz - sb;
        bool in_box = staged
            && (unsigned)lx < (unsigned)(sd - 1)
            && (unsigned)ly < (unsigned)(sd - 1)
            && (unsigned)lz < (unsigned)(sd - 1);

        if (in_box) {
            int i000 = soff + (lx * sd + ly) * sd + lz;
            int i100 = i000 + sd * sd;
            e0 = s_tbl[i000];          e1 = s_tbl[i000 + 1];
            e2 = s_tbl[i000 + sd];     e3 = s_tbl[i000 + sd + 1];
            e4 = s_tbl[i100];          e5 = s_tbl[i100 + 1];
            e6 = s_tbl[i100 + sd];     e7 = s_tbl[i100 + sd + 1];
        } else {
            unsigned hx0 = (unsigned)bx,       hx1 = (unsigned)(bx + 1);
            unsigned hy0 = (unsigned)by * 2654435761u;
            unsigned hy1 = (unsigned)(by + 1) * 2654435761u;
            unsigned hz0 = (unsigned)bz * 805459861u;
            unsigned hz1 = (unsigned)(bz + 1) * 805459861u;
            gather_global(gtbl, hx0, hx1, hy0, hy1, hz0, hz1,
                          e0, e1, e2, e3, e4, e5, e6, e7);
        }

        float ox = 1.0f - wx, oy = 1.0f - wy, oz = 1.0f - wz;
        float w0 = ox * oy * oz;
        float w1 = ox * oy * wz;
        float w2 = ox * wy * oz;
        float w3 = ox * wy * wz;
        float w4 = wx * oy * oz;
        float w5 = wx * oy * wz;
        float w6 = wx * wy * oz;
        float w7 = wx * wy * wz;

        float f0 = w0 * e0.x;
        float f1 = w0 * e0.y;
        f0 = fmaf(w1, e1.x, f0);  f1 = fmaf(w1, e1.y, f1);
        f0 = fmaf(w2, e2.x, f0);  f1 = fmaf(w2, e2.y, f1);
        f0 = fmaf(w3, e3.x, f0);  f1 = fmaf(w3, e3.y, f1);
        f0 = fmaf(w4, e4.x, f0);  f1 = fmaf(w4, e4.y, f1);
        f0 = fmaf(w5, e5.x, f0);  f1 = fmaf(w5, e5.y, f1);
        f0 = fmaf(w6, e6.x, f0);  f1 = fmaf(w6, e6.y, f1);
        f0 = fmaf(w7, e7.x, f0);  f1 = fmaf(w7, e7.y, f1);

        out2[w] = make_float2(f0, f1);   // w == p*16 + l  => coalesced
    }
}

extern "C" void kernel_launch(void* const* d_in, const int* in_sizes, int n_in,
                              void* d_out, int out_size)
{
    const float*  x   = (const float*)d_in[0];
    const float2* emb = (const float2*)d_in[1];
    float2*       out = (float2*)d_out;

    int npts = in_sizes[0] / 3;

    int nsm = 0;
    if (cudaDeviceGetAttribute(&nsm, cudaDevAttrMultiProcessorCount, 0) != cudaSuccess
        || nsm <= 0) {
        nsm = 148;
    }

    size_t smem_bytes = sizeof(float2) * TBL_N;   // 218,344 B
    cudaFuncSetAttribute(ingp_hash_kernel,
                         cudaFuncAttributeMaxDynamicSharedMemorySize,
                         (int)smem_bytes);

    ingp_hash_kernel<<<nsm, NTHREADS, smem_bytes>>>(x, emb, out, npts);
}

// round 6
// speedup vs baseline: 2.0642x; 1.5348x over previous
#include <cuda_runtime.h>
#include <cuda_bf16.h>
#include <cstdint>

// INGP hash-grid encoder, round 5: level-pure warps, compile-time level
// specialization, smem staging of levels 0-4 (152 KB), zero steady-state
// barriers, per-lane register accumulation + STG.128 stores.

#define NLEV 16
#define LOG2T 19
#define TSIZE (1u << LOG2T)
#define TMASK (TSIZE - 1u)

#define NSTAGED 5
#define TBL_N 18978              // 729+1331+2744+4913+9261 float2 entries
#define NTHREADS 1024

__constant__ float c_res[NLEV] = {
    16.f, 20.f, 25.f, 32.f, 40.f, 50.f, 64.f, 80.f,
    101.f, 128.f, 161.f, 203.f, 256.f, 322.f, 406.f, 512.f
};
__constant__ int c_sdim [NSTAGED] = { 9, 11, 14, 17, 21 };
__constant__ int c_sbase[NSTAGED] = { 8, 10, 12, 16, 20 };
__constant__ int c_soff [NSTAGED] = { 0, 729, 2060, 4804, 9717 };

__device__ __forceinline__ void gather_global(
    const float2* __restrict__ tbl,
    int bx, int by, int bz,
    float2& e0, float2& e1, float2& e2, float2& e3,
    float2& e4, float2& e5, float2& e6, float2& e7)
{
    unsigned hx0 = (unsigned)bx,       hx1 = (unsigned)(bx + 1);
    unsigned hy0 = (unsigned)by       * 2654435761u;
    unsigned hy1 = (unsigned)(by + 1) * 2654435761u;
    unsigned hz0 = (unsigned)bz       * 805459861u;
    unsigned hz1 = (unsigned)(bz + 1) * 805459861u;
    unsigned i0 = (hx0 ^ hy0 ^ hz0) & TMASK;
    unsigned i1 = (hx0 ^ hy0 ^ hz1) & TMASK;
    unsigned i2 = (hx0 ^ hy1 ^ hz0) & TMASK;
    unsigned i3 = (hx0 ^ hy1 ^ hz1) & TMASK;
    unsigned i4 = (hx1 ^ hy0 ^ hz0) & TMASK;
    unsigned i5 = (hx1 ^ hy0 ^ hz1) & TMASK;
    unsigned i6 = (hx1 ^ hy1 ^ hz0) & TMASK;
    unsigned i7 = (hx1 ^ hy1 ^ hz1) & TMASK;
    e0 = __ldg(tbl + i0);  e1 = __ldg(tbl + i1);
    e2 = __ldg(tbl + i2);  e3 = __ldg(tbl + i3);
    e4 = __ldg(tbl + i4);  e5 = __ldg(tbl + i5);
    e6 = __ldg(tbl + i6);  e7 = __ldg(tbl + i7);
}

template<int L>
__device__ __forceinline__ float2 do_level(
    float px, float py, float pz,
    const float2* __restrict__ emb,
    const float2* __restrict__ s_tbl)
{
    float res  = c_res[L];
    float grid = 2.0f / res;

    int bx = __float2int_rd((px + 1.0f) / grid);
    int by = __float2int_rd((py + 1.0f) / grid);
    int bz = __float2int_rd((pz + 1.0f) / grid);

    float wx = (px - ((float)bx * grid - 1.0f)) / grid;
    float wy = (py - ((float)by * grid - 1.0f)) / grid;
    float wz = (pz - ((float)bz * grid - 1.0f)) / grid;

    const float2* __restrict__ gtbl = emb + (size_t)L * TSIZE;

    float2 e0, e1, e2, e3, e4, e5, e6, e7;

    if (L < NSTAGED) {
        int sd = c_sdim[L], sb = c_sbase[L], soff = c_soff[L];
        int lx = bx - sb, ly = by - sb, lz = bz - sb;
        unsigned dm1 = (unsigned)(sd - 1);
        if ((unsigned)lx < dm1 && (unsigned)ly < dm1 && (unsigned)lz < dm1) {
            int i000 = soff + (lx * sd + ly) * sd + lz;
            int i100 = i000 + sd * sd;
            e0 = s_tbl[i000];          e1 = s_tbl[i000 + 1];
            e2 = s_tbl[i000 + sd];     e3 = s_tbl[i000 + sd + 1];
            e4 = s_tbl[i100];          e5 = s_tbl[i100 + 1];
            e6 = s_tbl[i100 + sd];     e7 = s_tbl[i100 + sd + 1];
        } else {
            // never taken for x in [0,1); correctness fallback only
            gather_global(gtbl, bx, by, bz, e0, e1, e2, e3, e4, e5, e6, e7);
        }
    } else {
        gather_global(gtbl, bx, by, bz, e0, e1, e2, e3, e4, e5, e6, e7);
    }

    float ox = 1.0f - wx, oy = 1.0f - wy, oz = 1.0f - wz;
    float w0 = ox * oy * oz;
    float w1 = ox * oy * wz;
    float w2 = ox * wy * oz;
    float w3 = ox * wy * wz;
    float w4 = wx * oy * oz;
    float w5 = wx * oy * wz;
    float w6 = wx * wy * oz;
    float w7 = wx * wy * wz;

    float f0 = w0 * e0.x;
    float f1 = w0 * e0.y;
    f0 = fmaf(w1, e1.x, f0);  f1 = fmaf(w1, e1.y, f1);
    f0 = fmaf(w2, e2.x, f0);  f1 = fmaf(w2, e2.y, f1);
    f0 = fmaf(w3, e3.x, f0);  f1 = fmaf(w3, e3.y, f1);
    f0 = fmaf(w4, e4.x, f0);  f1 = fmaf(w4, e4.y, f1);
    f0 = fmaf(w5, e5.x, f0);  f1 = fmaf(w5, e5.y, f1);
    f0 = fmaf(w6, e6.x, f0);  f1 = fmaf(w6, e6.y, f1);
    f0 = fmaf(w7, e7.x, f0);  f1 = fmaf(w7, e7.y, f1);
    return make_float2(f0, f1);
}

template<int C>
__device__ __forceinline__ void do_chunk(
    float px, float py, float pz,
    const float2* __restrict__ emb,
    const float2* __restrict__ s_tbl,
    float2* __restrict__ out2, int p)
{
    float2 a0 = do_level<C * 4 + 0>(px, py, pz, emb, s_tbl);
    float2 a1 = do_level<C * 4 + 1>(px, py, pz, emb, s_tbl);
    float2 a2 = do_level<C * 4 + 2>(px, py, pz, emb, s_tbl);
    float2 a3 = do_level<C * 4 + 3>(px, py, pz, emb, s_tbl);
    // lane's point owns bytes [p*128 + C*32, +32): two 16B stores
    float4* o = reinterpret_cast<float4*>(out2 + (size_t)p * NLEV + C * 4);
    o[0] = make_float4(a0.x, a0.y, a1.x, a1.y);
    o[1] = make_float4(a2.x, a2.y, a3.x, a3.y);
}

__global__ __launch_bounds__(NTHREADS, 1) void ingp_hash_kernel(
    const float*  __restrict__ x,      // (N,3)
    const float2* __restrict__ emb,    // (16, 2^19) float2
    float2*       __restrict__ out2,   // (N,16) float2
    int npts)
{
    extern __shared__ float2 s_tbl[];  // 18,978 entries = 151,824 B

    int tid = threadIdx.x;

    // ---------------- fill staged tables (levels 0-4, once per block) -------
    #pragma unroll
    for (int lv = 0; lv < NSTAGED; lv++) {
        int d   = c_sdim[lv];
        int n   = d * d * d;
        int off = c_soff[lv];
        int b   = c_sbase[lv];
        const float2* __restrict__ g = emb + (size_t)lv * TSIZE;
        for (int i = tid; i < n; i += NTHREADS) {
            int kk = i % d;
            int t  = i / d;
            int jj = t % d;
            int ii = t / d;
            unsigned h = ((unsigned)(b + ii)
                          ^ ((unsigned)(b + jj) * 2654435761u)
                          ^ ((unsigned)(b + kk) * 805459861u)) & TMASK;
            s_tbl[off + i] = __ldg(g + h);
        }
    }
    __syncthreads();   // the only barrier

    // ---------------- level-pure warp work loop ----------------
    int wid  = tid >> 5;
    int lane = tid & 31;
    int gwarp  = blockIdx.x * (NTHREADS / 32) + wid;
    int nwarps = gridDim.x * (NTHREADS / 32);

    int ngroups = (npts + 31) >> 5;
    long long nitems = (long long)ngroups * 4;   // (point-group, chunk) pairs

    for (long long it = gwarp; it < nitems; it += nwarps) {
        int pg    = (int)(it >> 2);
        int chunk = (int)(it & 3);
        int p = pg * 32 + lane;
        if (p >= npts) continue;

        float px = __ldg(x + 3 * p + 0);
        float py = __ldg(x + 3 * p + 1);
        float pz = __ldg(x + 3 * p + 2);
        px = fminf(fmaxf(px, -1.0f), 1.0f);
        py = fminf(fmaxf(py, -1.0f), 1.0f);
        pz = fminf(fmaxf(pz, -1.0f), 1.0f);

        switch (chunk) {
            case 0: do_chunk<0>(px, py, pz, emb, s_tbl, out2, p); break;
            case 1: do_chunk<1>(px, py, pz, emb, s_tbl, out2, p); break;
            case 2: do_chunk<2>(px, py, pz, emb, s_tbl, out2, p); break;
            default: do_chunk<3>(px, py, pz, emb, s_tbl, out2, p); break;
        }
    }
}

extern "C" void kernel_launch(void* const* d_in, const int* in_sizes, int n_in,
                              void* d_out, int out_size)
{
    const float*  x   = (const float*)d_in[0];
    const float2* emb = (const float2*)d_in[1];
    float2*       out = (float2*)d_out;

    int npts = in_sizes[0] / 3;

    int nsm = 0;
    if (cudaDeviceGetAttribute(&nsm, cudaDevAttrMultiProcessorCount, 0) != cudaSuccess
        || nsm <= 0) {
        nsm = 148;
    }

    size_t smem_bytes = sizeof(float2) * TBL_N;   // 151,824 B
    cudaFuncSetAttribute(ingp_hash_kernel,
                         cudaFuncAttributeMaxDynamicSharedMemorySize,
                         (int)smem_bytes);

    ingp_hash_kernel<<<nsm, NTHREADS, smem_bytes>>>(x, emb, out, npts);
}

// round 8
// speedup vs baseline: 2.5359x; 1.2285x over previous
#include <cuda_runtime.h>
#include <cuda_bf16.h>
#include <cstdint>

// INGP hash-grid encoder, round 6: spatial counting-sort (32^3 bins over [0,1))
// so each warp processes 32 spatially-adjacent points -> coarse/mid levels
// coalesce to a few cache lines per gather. No smem staging, no barriers in
// the main kernel, level-pure warps via compile-time 2-level chunks.

#define NLEV 16
#define LOG2T 19
#define TSIZE (1u << LOG2T)
#define TMASK (TSIZE - 1u)

#define NBINS_AXIS 32
#define NBINS (NBINS_AXIS * NBINS_AXIS * NBINS_AXIS)   // 32768
#define MAXPTS (1 << 21)

__constant__ float c_res[NLEV] = {
    16.f, 20.f, 25.f, 32.f, 40.f, 50.f, 64.f, 80.f,
    101.f, 128.f, 161.f, 203.f, 256.f, 322.f, 406.f, 512.f
};

__device__ int            d_hist[NBINS];
__device__ unsigned short d_keys[MAXPTS];
__device__ int            d_order[MAXPTS];
__device__ float          d_xs[MAXPTS * 3];

// ---------------------------------------------------------------- sort stages
__global__ void k_zero_hist() {
    int i = blockIdx.x * blockDim.x + threadIdx.x;
    if (i < NBINS) d_hist[i] = 0;
}

__global__ void k_key_hist(const float* __restrict__ x, int npts) {
    int p = blockIdx.x * blockDim.x + threadIdx.x;
    if (p >= npts) return;
    float px = x[3 * p + 0], py = x[3 * p + 1], pz = x[3 * p + 2];
    // binning only (no effect on math): clamp into [0,1) then 5 bits/axis
    int ix = (int)(fminf(fmaxf(px, 0.0f), 0.999999f) * 32.0f);
    int iy = (int)(fminf(fmaxf(py, 0.0f), 0.999999f) * 32.0f);
    int iz = (int)(fminf(fmaxf(pz, 0.0f), 0.999999f) * 32.0f);
    unsigned key = ((unsigned)ix << 10) | ((unsigned)iy << 5) | (unsigned)iz;
    d_keys[p] = (unsigned short)key;
    atomicAdd(&d_hist[key], 1);
}

__global__ __launch_bounds__(1024) void k_scan() {
    __shared__ int tsum[1024];
    int t = threadIdx.x;
    int base = t * 32;
    int s = 0;
    #pragma unroll
    for (int i = 0; i < 32; i++) s += d_hist[base + i];
    tsum[t] = s;
    __syncthreads();
    // Hillis-Steele inclusive scan over 1024 partials
    for (int off = 1; off < 1024; off <<= 1) {
        int v = (t >= off) ? tsum[t - off] : 0;
        __syncthreads();
        tsum[t] += v;
        __syncthreads();
    }
    int run = tsum[t] - s;   // exclusive prefix of this thread's 32-bin chunk
    #pragma unroll
    for (int i = 0; i < 32; i++) {
        int c = d_hist[base + i];
        d_hist[base + i] = run;
        run += c;
    }
}

__global__ void k_scatter(const float* __restrict__ x, int npts) {
    int p = blockIdx.x * blockDim.x + threadIdx.x;
    if (p >= npts) return;
    unsigned key = d_keys[p];
    int pos = atomicAdd(&d_hist[key], 1);
    d_order[pos] = p;
    d_xs[3 * pos + 0] = x[3 * p + 0];
    d_xs[3 * pos + 1] = x[3 * p + 1];
    d_xs[3 * pos + 2] = x[3 * p + 2];
}

// ---------------------------------------------------------------- main kernel
__device__ __forceinline__ void gather_global(
    const float2* __restrict__ tbl,
    int bx, int by, int bz,
    float2& e0, float2& e1, float2& e2, float2& e3,
    float2& e4, float2& e5, float2& e6, float2& e7)
{
    unsigned hx0 = (unsigned)bx,       hx1 = (unsigned)(bx + 1);
    unsigned hy0 = (unsigned)by       * 2654435761u;
    unsigned hy1 = (unsigned)(by + 1) * 2654435761u;
    unsigned hz0 = (unsigned)bz       * 805459861u;
    unsigned hz1 = (unsigned)(bz + 1) * 805459861u;
    unsigned i0 = (hx0 ^ hy0 ^ hz0) & TMASK;
    unsigned i1 = (hx0 ^ hy0 ^ hz1) & TMASK;
    unsigned i2 = (hx0 ^ hy1 ^ hz0) & TMASK;
    unsigned i3 = (hx0 ^ hy1 ^ hz1) & TMASK;
    unsigned i4 = (hx1 ^ hy0 ^ hz0) & TMASK;
    unsigned i5 = (hx1 ^ hy0 ^ hz1) & TMASK;
    unsigned i6 = (hx1 ^ hy1 ^ hz0) & TMASK;
    unsigned i7 = (hx1 ^ hy1 ^ hz1) & TMASK;
    e0 = __ldg(tbl + i0);  e1 = __ldg(tbl + i1);
    e2 = __ldg(tbl + i2);  e3 = __ldg(tbl + i3);
    e4 = __ldg(tbl + i4);  e5 = __ldg(tbl + i5);
    e6 = __ldg(tbl + i6);  e7 = __ldg(tbl + i7);
}

template<int L>
__device__ __forceinline__ float2 do_level(
    float px, float py, float pz, const float2* __restrict__ emb)
{
    float res  = c_res[L];
    float grid = 2.0f / res;

    int bx = __float2int_rd((px + 1.0f) / grid);
    int by = __float2int_rd((py + 1.0f) / grid);
    int bz = __float2int_rd((pz + 1.0f) / grid);

    float wx = (px - ((float)bx * grid - 1.0f)) / grid;
    float wy = (py - ((float)by * grid - 1.0f)) / grid;
    float wz = (pz - ((float)bz * grid - 1.0f)) / grid;

    const float2* __restrict__ gtbl = emb + (size_t)L * TSIZE;
    float2 e0, e1, e2, e3, e4, e5, e6, e7;
    gather_global(gtbl, bx, by, bz, e0, e1, e2, e3, e4, e5, e6, e7);

    float ox = 1.0f - wx, oy = 1.0f - wy, oz = 1.0f - wz;
    float w0 = ox * oy * oz;
    float w1 = ox * oy * wz;
    float w2 = ox * wy * oz;
    float w3 = ox * wy * wz;
    float w4 = wx * oy * oz;
    float w5 = wx * oy * wz;
    float w6 = wx * wy * oz;
    float w7 = wx * wy * wz;

    float f0 = w0 * e0.x;
    float f1 = w0 * e0.y;
    f0 = fmaf(w1, e1.x, f0);  f1 = fmaf(w1, e1.y, f1);
    f0 = fmaf(w2, e2.x, f0);  f1 = fmaf(w2, e2.y, f1);
    f0 = fmaf(w3, e3.x, f0);  f1 = fmaf(w3, e3.y, f1);
    f0 = fmaf(w4, e4.x, f0);  f1 = fmaf(w4, e4.y, f1);
    f0 = fmaf(w5, e5.x, f0);  f1 = fmaf(w5, e5.y, f1);
    f0 = fmaf(w6, e6.x, f0);  f1 = fmaf(w6, e6.y, f1);
    f0 = fmaf(w7, e7.x, f0);  f1 = fmaf(w7, e7.y, f1);
    return make_float2(f0, f1);
}

template<int C>
__device__ __forceinline__ void do_pair(
    float px, float py, float pz,
    const float2* __restrict__ emb,
    float4* __restrict__ out4, int p)
{
    float2 a0 = do_level<C * 2 + 0>(px, py, pz, emb);
    float2 a1 = do_level<C * 2 + 1>(px, py, pz, emb);
    out4[(size_t)p * 8 + C] = make_float4(a0.x, a0.y, a1.x, a1.y);
}

__global__ __launch_bounds__(256) void k_main(
    const float2* __restrict__ emb,
    float4*       __restrict__ out4,
    int npts)
{
    // one warp = 32 sorted points x one 2-level chunk
    int gw   = blockIdx.x * (blockDim.x >> 5) + (threadIdx.x >> 5);
    int lane = threadIdx.x & 31;
    int pg = gw >> 3;          // sorted point group
    int c  = gw & 7;           // level-pair chunk
    int i  = pg * 32 + lane;   // sorted index
    if (i >= npts) return;

    int p = d_order[i];
    float px = d_xs[3 * i + 0];
    float py = d_xs[3 * i + 1];
    float pz = d_xs[3 * i + 2];
    px = fminf(fmaxf(px, -1.0f), 1.0f);
    py = fminf(fmaxf(py, -1.0f), 1.0f);
    pz = fminf(fmaxf(pz, -1.0f), 1.0f);

    switch (c) {
        case 0: do_pair<0>(px, py, pz, emb, out4, p); break;
        case 1: do_pair<1>(px, py, pz, emb, out4, p); break;
        case 2: do_pair<2>(px, py, pz, emb, out4, p); break;
        case 3: do_pair<3>(px, py, pz, emb, out4, p); break;
        case 4: do_pair<4>(px, py, pz, emb, out4, p); break;
        case 5: do_pair<5>(px, py, pz, emb, out4, p); break;
        case 6: do_pair<6>(px, py, pz, emb, out4, p); break;
        default: do_pair<7>(px, py, pz, emb, out4, p); break;
    }
}

// fallback for npts > MAXPTS (never expected here): unsorted direct kernel
__global__ __launch_bounds__(256) void k_fallback(
    const float* __restrict__ x, const float2* __restrict__ emb,
    float2* __restrict__ out2, int npts)
{
    long long tid = (long long)blockIdx.x * blockDim.x + threadIdx.x;
    int p = (int)(tid >> 4);
    if (p >= npts) return;
    int l = (int)(tid & 15);
    float px = x[3*p], py = x[3*p+1], pz = x[3*p+2];
    px = fminf(fmaxf(px, -1.0f), 1.0f);
    py = fminf(fmaxf(py, -1.0f), 1.0f);
    pz = fminf(fmaxf(pz, -1.0f), 1.0f);
    float res = c_res[l];
    float grid = 2.0f / res;
    int bx = __float2int_rd((px + 1.0f) / grid);
    int by = __float2int_rd((py + 1.0f) / grid);
    int bz = __float2int_rd((pz + 1.0f) / grid);
    float wx = (px - ((float)bx * grid - 1.0f)) / grid;
    float wy = (py - ((float)by * grid - 1.0f)) / grid;
    float wz = (pz - ((float)bz * grid - 1.0f)) / grid;
    const float2* gtbl = emb + (size_t)l * TSIZE;
    float2 e0,e1,e2,e3,e4,e5,e6,e7;
    gather_global(gtbl, bx, by, bz, e0,e1,e2,e3,e4,e5,e6,e7);
    float ox = 1.0f-wx, oy = 1.0f-wy, oz = 1.0f-wz;
    float f0 = ox*oy*oz*e0.x, f1 = ox*oy*oz*e0.y;
    f0 = fmaf(ox*oy*wz, e1.x, f0); f1 = fmaf(ox*oy*wz, e1.y, f1);
    f0 = fmaf(ox*wy*oz, e2.x, f0); f1 = fmaf(ox*wy*oz, e2.y, f1);
    f0 = fmaf(ox*wy*wz, e3.x, f0); f1 = fmaf(ox*wy*wz, e3.y, f1);
    f0 = fmaf(wx*oy*oz, e4.x, f0); f1 = fmaf(wx*oy*oz, e4.y, f1);
    f0 = fmaf(wx*oy*wz, e5.x, f0); f1 = fmaf(wx*oy*wz, e5.y, f1);
    f0 = fmaf(wx*wy*oz, e6.x, f0); f1 = fmaf(wx*wy*oz, e6.y, f1);
    f0 = fmaf(wx*wy*wz, e7.x, f0); f1 = fmaf(wx*wy*wz, e7.y, f1);
    out2[tid] = make_float2(f0, f1);
}

extern "C" void kernel_launch(void* const* d_in, const int* in_sizes, int n_in,
                              void* d_out, int out_size)
{
    const float*  x   = (const float*)d_in[0];
    const float2* emb = (const float2*)d_in[1];

    int npts = in_sizes[0] / 3;

    if (npts > MAXPTS) {
        long long total = (long long)npts * NLEV;
        int blocks = (int)((total + 255) / 256);
        k_fallback<<<blocks, 256>>>(x, emb, (float2*)d_out, npts);
        return;
    }

    // 1) spatial counting sort
    k_zero_hist<<<(NBINS + 1023) / 1024, 1024>>>();
    k_key_hist<<<(npts + 255) / 256, 256>>>(x, npts);
    k_scan<<<1, 1024>>>();
    k_scatter<<<(npts + 255) / 256, 256>>>(x, npts);

    // 2) coherent main kernel: one warp per (32-point group, 2-level chunk)
    int ngroups = (npts + 31) / 32;
    long long nwarps = (long long)ngroups * 8;
    long long nthreads = nwarps * 32;
    int blocks = (int)((nthreads + 255) / 256);
    k_main<<<blocks, 256>>>(emb, (float4*)d_out, npts);
}

// round 11
// speedup vs baseline: 2.6411x; 1.0415x over previous
#include <cuda_runtime.h>
#include <cuda_bf16.h>
#include <cstdint>

// INGP hash-grid encoder, round 9 design (resubmit after infra failure):
// spatial counting-sort (32^3 bins) with a packed float4 payload
// (x,y,z,orig_idx) -> 1 scattered STG.128 per point instead of 4 scattered
// stores; keys recomputed instead of stored. Main kernel: warp = 32 sorted
// points x one 2-level chunk (compile-time levels, level-pure warps).

#define NLEV 16
#define LOG2T 19
#define TSIZE (1u << LOG2T)
#define TMASK (TSIZE - 1u)

#define NBINS_AXIS 32
#define NBINS (NBINS_AXIS * NBINS_AXIS * NBINS_AXIS)   // 32768
#define MAXPTS (1 << 21)

__constant__ float c_res[NLEV] = {
    16.f, 20.f, 25.f, 32.f, 40.f, 50.f, 64.f, 80.f,
    101.f, 128.f, 161.f, 203.f, 256.f, 322.f, 406.f, 512.f
};

__device__ int    d_hist[NBINS];
__device__ float4 d_xs4[MAXPTS];

__device__ __forceinline__ unsigned bin_key(float px, float py, float pz) {
    int ix = (int)(fminf(fmaxf(px, 0.0f), 0.999999f) * 32.0f);
    int iy = (int)(fminf(fmaxf(py, 0.0f), 0.999999f) * 32.0f);
    int iz = (int)(fminf(fmaxf(pz, 0.0f), 0.999999f) * 32.0f);
    return ((unsigned)ix << 10) | ((unsigned)iy << 5) | (unsigned)iz;
}

// ---------------------------------------------------------------- sort stages
__global__ void k_zero_hist() {
    int i = blockIdx.x * blockDim.x + threadIdx.x;
    if (i < NBINS) d_hist[i] = 0;
}

__global__ void k_key_hist(const float* __restrict__ x, int npts) {
    int p = blockIdx.x * blockDim.x + threadIdx.x;
    if (p >= npts) return;
    unsigned key = bin_key(x[3 * p + 0], x[3 * p + 1], x[3 * p + 2]);
    atomicAdd(&d_hist[key], 1);
}

__global__ __launch_bounds__(1024) void k_scan() {
    __shared__ int tsum[1024];
    int t = threadIdx.x;
    int base = t * 32;
    int s = 0;
    #pragma unroll
    for (int i = 0; i < 32; i++) s += d_hist[base + i];
    tsum[t] = s;
    __syncthreads();
    for (int off = 1; off < 1024; off <<= 1) {
        int v = (t >= off) ? tsum[t - off] : 0;
        __syncthreads();
        tsum[t] += v;
        __syncthreads();
    }
    int run = tsum[t] - s;   // exclusive prefix of this thread's 32-bin chunk
    #pragma unroll
    for (int i = 0; i < 32; i++) {
        int c = d_hist[base + i];
        d_hist[base + i] = run;
        run += c;
    }
}

__global__ void k_scatter(const float* __restrict__ x, int npts) {
    int p = blockIdx.x * blockDim.x + threadIdx.x;
    if (p >= npts) return;
    float px = x[3 * p + 0], py = x[3 * p + 1], pz = x[3 * p + 2];
    unsigned key = bin_key(px, py, pz);
    int pos = atomicAdd(&d_hist[key], 1);
    d_xs4[pos] = make_float4(px, py, pz, __int_as_float(p));
}

// ---------------------------------------------------------------- main kernel
__device__ __forceinline__ void gather_global(
    const float2* __restrict__ tbl,
    int bx, int by, int bz,
    float2& e0, float2& e1, float2& e2, float2& e3,
    float2& e4, float2& e5, float2& e6, float2& e7)
{
    unsigned hx0 = (unsigned)bx,       hx1 = (unsigned)(bx + 1);
    unsigned hy0 = (unsigned)by       * 2654435761u;
    unsigned hy1 = (unsigned)(by + 1) * 2654435761u;
    unsigned hz0 = (unsigned)bz       * 805459861u;
    unsigned hz1 = (unsigned)(bz + 1) * 805459861u;
    unsigned i0 = (hx0 ^ hy0 ^ hz0) & TMASK;
    unsigned i1 = (hx0 ^ hy0 ^ hz1) & TMASK;
    unsigned i2 = (hx0 ^ hy1 ^ hz0) & TMASK;
    unsigned i3 = (hx0 ^ hy1 ^ hz1) & TMASK;
    unsigned i4 = (hx1 ^ hy0 ^ hz0) & TMASK;
    unsigned i5 = (hx1 ^ hy0 ^ hz1) & TMASK;
    unsigned i6 = (hx1 ^ hy1 ^ hz0) & TMASK;
    unsigned i7 = (hx1 ^ hy1 ^ hz1) & TMASK;
    e0 = __ldg(tbl + i0);  e1 = __ldg(tbl + i1);
    e2 = __ldg(tbl + i2);  e3 = __ldg(tbl + i3);
    e4 = __ldg(tbl + i4);  e5 = __ldg(tbl + i5);
    e6 = __ldg(tbl + i6);  e7 = __ldg(tbl + i7);
}

template<int L>
__device__ __forceinline__ float2 do_level(
    float px, float py, float pz, const float2* __restrict__ emb)
{
    float res  = c_res[L];
    float grid = 2.0f / res;

    int bx = __float2int_rd((px + 1.0f) / grid);
    int by = __float2int_rd((py + 1.0f) / grid);
    int bz = __float2int_rd((pz + 1.0f) / grid);

    float wx = (px - ((float)bx * grid - 1.0f)) / grid;
    float wy = (py - ((float)by * grid - 1.0f)) / grid;
    float wz = (pz - ((float)bz * grid - 1.0f)) / grid;

    const float2* __restrict__ gtbl = emb + (size_t)L * TSIZE;
    float2 e0, e1, e2, e3, e4, e5, e6, e7;
    gather_global(gtbl, bx, by, bz, e0, e1, e2, e3, e4, e5, e6, e7);

    float ox = 1.0f - wx, oy = 1.0f - wy, oz = 1.0f - wz;
    float w0 = ox * oy * oz;
    float w1 = ox * oy * wz;
    float w2 = ox * wy * oz;
    float w3 = ox * wy * wz;
    float w4 = wx * oy * oz;
    float w5 = wx * oy * wz;
    float w6 = wx * wy * oz;
    float w7 = wx * wy * wz;

    float f0 = w0 * e0.x;
    float f1 = w0 * e0.y;
    f0 = fmaf(w1, e1.x, f0);  f1 = fmaf(w1, e1.y, f1);
    f0 = fmaf(w2, e2.x, f0);  f1 = fmaf(w2, e2.y, f1);
    f0 = fmaf(w3, e3.x, f0);  f1 = fmaf(w3, e3.y, f1);
    f0 = fmaf(w4, e4.x, f0);  f1 = fmaf(w4, e4.y, f1);
    f0 = fmaf(w5, e5.x, f0);  f1 = fmaf(w5, e5.y, f1);
    f0 = fmaf(w6, e6.x, f0);  f1 = fmaf(w6, e6.y, f1);
    f0 = fmaf(w7, e7.x, f0);  f1 = fmaf(w7, e7.y, f1);
    return make_float2(f0, f1);
}

template<int C>
__device__ __forceinline__ void do_pair(
    float px, float py, float pz,
    const float2* __restrict__ emb,
    float4* __restrict__ out4, int p)
{
    float2 a0 = do_level<C * 2 + 0>(px, py, pz, emb);
    float2 a1 = do_level<C * 2 + 1>(px, py, pz, emb);
    out4[(size_t)p * 8 + C] = make_float4(a0.x, a0.y, a1.x, a1.y);
}

__global__ __launch_bounds__(256) void k_main(
    const float2* __restrict__ emb,
    float4*       __restrict__ out4,
    int npts)
{
    // one warp = 32 sorted points x one 2-level chunk
    int gw   = blockIdx.x * (blockDim.x >> 5) + (threadIdx.x >> 5);
    int lane = threadIdx.x & 31;
    int pg = gw >> 3;          // sorted point group
    int c  = gw & 7;           // level-pair chunk
    int i  = pg * 32 + lane;   // sorted index
    if (i >= npts) return;

    float4 v = d_xs4[i];
    int p = __float_as_int(v.w);
    float px = fminf(fmaxf(v.x, -1.0f), 1.0f);
    float py = fminf(fmaxf(v.y, -1.0f), 1.0f);
    float pz = fminf(fmaxf(v.z, -1.0f), 1.0f);

    switch (c) {
        case 0: do_pair<0>(px, py, pz, emb, out4, p); break;
        case 1: do_pair<1>(px, py, pz, emb, out4, p); break;
        case 2: do_pair<2>(px, py, pz, emb, out4, p); break;
        case 3: do_pair<3>(px, py, pz, emb, out4, p); break;
        case 4: do_pair<4>(px, py, pz, emb, out4, p); break;
        case 5: do_pair<5>(px, py, pz, emb, out4, p); break;
        case 6: do_pair<6>(px, py, pz, emb, out4, p); break;
        default: do_pair<7>(px, py, pz, emb, out4, p); break;
    }
}

// fallback for npts > MAXPTS (not expected): unsorted direct kernel
__global__ __launch_bounds__(256) void k_fallback(
    const float* __restrict__ x, const float2* __restrict__ emb,
    float2* __restrict__ out2, int npts)
{
    long long tid = (long long)blockIdx.x * blockDim.x + threadIdx.x;
    int p = (int)(tid >> 4);
    if (p >= npts) return;
    int l = (int)(tid & 15);
    float px = x[3*p], py = x[3*p+1], pz = x[3*p+2];
    px = fminf(fmaxf(px, -1.0f), 1.0f);
    py = fminf(fmaxf(py, -1.0f), 1.0f);
    pz = fminf(fmaxf(pz, -1.0f), 1.0f);
    float res = c_res[l];
    float grid = 2.0f / res;
    int bx = __float2int_rd((px + 1.0f) / grid);
    int by = __float2int_rd((py + 1.0f) / grid);
    int bz = __float2int_rd((pz + 1.0f) / grid);
    float wx = (px - ((float)bx * grid - 1.0f)) / grid;
    float wy = (py - ((float)by * grid - 1.0f)) / grid;
    float wz = (pz - ((float)bz * grid - 1.0f)) / grid;
    const float2* gtbl = emb + (size_t)l * TSIZE;
    float2 e0,e1,e2,e3,e4,e5,e6,e7;
    gather_global(gtbl, bx, by, bz, e0,e1,e2,e3,e4,e5,e6,e7);
    float ox = 1.0f-wx, oy = 1.0f-wy, oz = 1.0f-wz;
    float f0 = ox*oy*oz*e0.x, f1 = ox*oy*oz*e0.y;
    f0 = fmaf(ox*oy*wz, e1.x, f0); f1 = fmaf(ox*oy*wz, e1.y, f1);
    f0 = fmaf(ox*wy*oz, e2.x, f0); f1 = fmaf(ox*wy*oz, e2.y, f1);
    f0 = fmaf(ox*wy*wz, e3.x, f0); f1 = fmaf(ox*wy*wz, e3.y, f1);
    f0 = fmaf(wx*oy*oz, e4.x, f0); f1 = fmaf(wx*oy*oz, e4.y, f1);
    f0 = fmaf(wx*oy*wz, e5.x, f0); f1 = fmaf(wx*oy*wz, e5.y, f1);
    f0 = fmaf(wx*wy*oz, e6.x, f0); f1 = fmaf(wx*wy*oz, e6.y, f1);
    f0 = fmaf(wx*wy*wz, e7.x, f0); f1 = fmaf(wx*wy*wz, e7.y, f1);
    out2[tid] = make_float2(f0, f1);
}

extern "C" void kernel_launch(void* const* d_in, const int* in_sizes, int n_in,
                              void* d_out, int out_size)
{
    const float*  x   = (const float*)d_in[0];
    const float2* emb = (const float2*)d_in[1];

    int npts = in_sizes[0] / 3;

    if (npts > MAXPTS) {
        long long total = (long long)npts * NLEV;
        int blocks = (int)((total + 255) / 256);
        k_fallback<<<blocks, 256>>>(x, emb, (float2*)d_out, npts);
        return;
    }

    // 1) spatial counting sort (packed payload)
    k_zero_hist<<<(NBINS + 1023) / 1024, 1024>>>();
    k_key_hist<<<(npts + 255) / 256, 256>>>(x, npts);
    k_scan<<<1, 1024>>>();
    k_scatter<<<(npts + 255) / 256, 256>>>(x, npts);

    // 2) coherent main kernel
    int ngroups = (npts + 31) / 32;
    long long nwarps = (long long)ngroups * 8;
    long long nthreads = nwarps * 32;
    int blocks = (int)((nthreads + 255) / 256);
    k_main<<<blocks, 256>>>(emb, (float4*)d_out, npts);
}

// round 13
// speedup vs baseline: 2.8339x; 1.0730x over previous
#include <cuda_runtime.h>
#include <cuda_bf16.h>
#include <cstdint>

// INGP hash-grid encoder, round 12: counting-sorted coherent gather +
//  - 4-level chunks per warp -> 32 B full-sector output stores
//  - __ldcs streaming loads for fine levels (no-reuse) to protect L1
//  - ILP=2 scatter

#define NLEV 16
#define LOG2T 19
#define TSIZE (1u << LOG2T)
#define TMASK (TSIZE - 1u)

#define NBINS_AXIS 32
#define NBINS (NBINS_AXIS * NBINS_AXIS * NBINS_AXIS)   // 32768
#define MAXPTS (1 << 21)

__constant__ float c_res[NLEV] = {
    16.f, 20.f, 25.f, 32.f, 40.f, 50.f, 64.f, 80.f,
    101.f, 128.f, 161.f, 203.f, 256.f, 322.f, 406.f, 512.f
};

__device__ int    d_hist[NBINS];
__device__ float4 d_xs4[MAXPTS];

__device__ __forceinline__ unsigned bin_key(float px, float py, float pz) {
    int ix = (int)(fminf(fmaxf(px, 0.0f), 0.999999f) * 32.0f);
    int iy = (int)(fminf(fmaxf(py, 0.0f), 0.999999f) * 32.0f);
    int iz = (int)(fminf(fmaxf(pz, 0.0f), 0.999999f) * 32.0f);
    return ((unsigned)ix << 10) | ((unsigned)iy << 5) | (unsigned)iz;
}

// ---------------------------------------------------------------- sort stages
__global__ void k_zero_hist() {
    int i = blockIdx.x * blockDim.x + threadIdx.x;
    if (i < NBINS) d_hist[i] = 0;
}

__global__ void k_key_hist(const float* __restrict__ x, int npts) {
    int p = blockIdx.x * blockDim.x + threadIdx.x;
    if (p >= npts) return;
    unsigned key = bin_key(x[3 * p + 0], x[3 * p + 1], x[3 * p + 2]);
    atomicAdd(&d_hist[key], 1);
}

__global__ __launch_bounds__(1024) void k_scan() {
    __shared__ int tsum[1024];
    int t = threadIdx.x;
    int base = t * 32;
    int s = 0;
    #pragma unroll
    for (int i = 0; i < 32; i++) s += d_hist[base + i];
    tsum[t] = s;
    __syncthreads();
    for (int off = 1; off < 1024; off <<= 1) {
        int v = (t >= off) ? tsum[t - off] : 0;
        __syncthreads();
        tsum[t] += v;
        __syncthreads();
    }
    int run = tsum[t] - s;   // exclusive prefix of this thread's 32-bin chunk
    #pragma unroll
    for (int i = 0; i < 32; i++) {
        int c = d_hist[base + i];
        d_hist[base + i] = run;
        run += c;
    }
}

__global__ void k_scatter(const float* __restrict__ x, int npts) {
    int p0 = (blockIdx.x * blockDim.x + threadIdx.x) * 2;
    if (p0 >= npts) return;
    // point A
    float ax = x[3 * p0 + 0], ay = x[3 * p0 + 1], az = x[3 * p0 + 2];
    bool hasB = (p0 + 1) < npts;
    float bx_ = 0.f, by_ = 0.f, bz_ = 0.f;
    if (hasB) { bx_ = x[3 * p0 + 3]; by_ = x[3 * p0 + 4]; bz_ = x[3 * p0 + 5]; }
    unsigned ka = bin_key(ax, ay, az);
    int pa = atomicAdd(&d_hist[ka], 1);
    if (hasB) {
        unsigned kb = bin_key(bx_, by_, bz_);
        int pb = atomicAdd(&d_hist[kb], 1);
        d_xs4[pb] = make_float4(bx_, by_, bz_, __int_as_float(p0 + 1));
    }
    d_xs4[pa] = make_float4(ax, ay, az, __int_as_float(p0));
}

// ---------------------------------------------------------------- main kernel
template<bool STREAM>
__device__ __forceinline__ float2 tload(const float2* __restrict__ p) {
    if (STREAM) return __ldcs(p);
    return __ldg(p);
}

template<int L>
__device__ __forceinline__ float2 do_level(
    float px, float py, float pz, const float2* __restrict__ emb)
{
    constexpr bool STREAM = (L >= 10);   // fine levels: no reuse, evict-first
    float res  = c_res[L];
    float grid = 2.0f / res;

    int bx = __float2int_rd((px + 1.0f) / grid);
    int by = __float2int_rd((py + 1.0f) / grid);
    int bz = __float2int_rd((pz + 1.0f) / grid);

    float wx = (px - ((float)bx * grid - 1.0f)) / grid;
    float wy = (py - ((float)by * grid - 1.0f)) / grid;
    float wz = (pz - ((float)bz * grid - 1.0f)) / grid;

    const float2* __restrict__ gtbl = emb + (size_t)L * TSIZE;

    unsigned hx0 = (unsigned)bx,       hx1 = (unsigned)(bx + 1);
    unsigned hy0 = (unsigned)by       * 2654435761u;
    unsigned hy1 = (unsigned)(by + 1) * 2654435761u;
    unsigned hz0 = (unsigned)bz       * 805459861u;
    unsigned hz1 = (unsigned)(bz + 1) * 805459861u;
    unsigned i0 = (hx0 ^ hy0 ^ hz0) & TMASK;
    unsigned i1 = (hx0 ^ hy0 ^ hz1) & TMASK;
    unsigned i2 = (hx0 ^ hy1 ^ hz0) & TMASK;
    unsigned i3 = (hx0 ^ hy1 ^ hz1) & TMASK;
    unsigned i4 = (hx1 ^ hy0 ^ hz0) & TMASK;
    unsigned i5 = (hx1 ^ hy0 ^ hz1) & TMASK;
    unsigned i6 = (hx1 ^ hy1 ^ hz0) & TMASK;
    unsigned i7 = (hx1 ^ hy1 ^ hz1) & TMASK;

    float2 e0 = tload<STREAM>(gtbl + i0);
    float2 e1 = tload<STREAM>(gtbl + i1);
    float2 e2 = tload<STREAM>(gtbl + i2);
    float2 e3 = tload<STREAM>(gtbl + i3);
    float2 e4 = tload<STREAM>(gtbl + i4);
    float2 e5 = tload<STREAM>(gtbl + i5);
    float2 e6 = tload<STREAM>(gtbl + i6);
    float2 e7 = tload<STREAM>(gtbl + i7);

    float ox = 1.0f - wx, oy = 1.0f - wy, oz = 1.0f - wz;
    float w0 = ox * oy * oz;
    float w1 = ox * oy * wz;
    float w2 = ox * wy * oz;
    float w3 = ox * wy * wz;
    float w4 = wx * oy * oz;
    float w5 = wx * oy * wz;
    float w6 = wx * wy * oz;
    float w7 = wx * wy * wz;

    float f0 = w0 * e0.x;
    float f1 = w0 * e0.y;
    f0 = fmaf(w1, e1.x, f0);  f1 = fmaf(w1, e1.y, f1);
    f0 = fmaf(w2, e2.x, f0);  f1 = fmaf(w2, e2.y, f1);
    f0 = fmaf(w3, e3.x, f0);  f1 = fmaf(w3, e3.y, f1);
    f0 = fmaf(w4, e4.x, f0);  f1 = fmaf(w4, e4.y, f1);
    f0 = fmaf(w5, e5.x, f0);  f1 = fmaf(w5, e5.y, f1);
    f0 = fmaf(w6, e6.x, f0);  f1 = fmaf(w6, e6.y, f1);
    f0 = fmaf(w7, e7.x, f0);  f1 = fmaf(w7, e7.y, f1);
    return make_float2(f0, f1);
}

template<int C>
__device__ __forceinline__ void do_quad(
    float px, float py, float pz,
    const float2* __restrict__ emb,
    float4* __restrict__ out4, int p)
{
    float2 a0 = do_level<C * 4 + 0>(px, py, pz, emb);
    float2 a1 = do_level<C * 4 + 1>(px, py, pz, emb);
    float2 a2 = do_level<C * 4 + 2>(px, py, pz, emb);
    float2 a3 = do_level<C * 4 + 3>(px, py, pz, emb);
    // 32 B into one sector: two consecutive STG.128
    float4* o = out4 + (size_t)p * 8 + C * 2;
    o[0] = make_float4(a0.x, a0.y, a1.x, a1.y);
    o[1] = make_float4(a2.x, a2.y, a3.x, a3.y);
}

__global__ __launch_bounds__(256) void k_main(
    const float2* __restrict__ emb,
    float4*       __restrict__ out4,
    int npts)
{
    // one warp = 32 sorted points x one 4-level chunk
    int gw   = blockIdx.x * (blockDim.x >> 5) + (threadIdx.x >> 5);
    int lane = threadIdx.x & 31;
    int pg = gw >> 2;          // sorted point group
    int c  = gw & 3;           // 4-level chunk
    int i  = pg * 32 + lane;   // sorted index
    if (i >= npts) return;

    float4 v = d_xs4[i];
    int p = __float_as_int(v.w);
    float px = fminf(fmaxf(v.x, -1.0f), 1.0f);
    float py = fminf(fmaxf(v.y, -1.0f), 1.0f);
    float pz = fminf(fmaxf(v.z, -1.0f), 1.0f);

    switch (c) {
        case 0: do_quad<0>(px, py, pz, emb, out4, p); break;
        case 1: do_quad<1>(px, py, pz, emb, out4, p); break;
        case 2: do_quad<2>(px, py, pz, emb, out4, p); break;
        default: do_quad<3>(px, py, pz, emb, out4, p); break;
    }
}

// fallback for npts > MAXPTS (not expected): unsorted direct kernel
__global__ __launch_bounds__(256) void k_fallback(
    const float* __restrict__ x, const float2* __restrict__ emb,
    float2* __restrict__ out2, int npts)
{
    long long tid = (long long)blockIdx.x * blockDim.x + threadIdx.x;
    int p = (int)(tid >> 4);
    if (p >= npts) return;
    int l = (int)(tid & 15);
    float px = x[3*p], py = x[3*p+1], pz = x[3*p+2];
    px = fminf(fmaxf(px, -1.0f), 1.0f);
    py = fminf(fmaxf(py, -1.0f), 1.0f);
    pz = fminf(fmaxf(pz, -1.0f), 1.0f);
    float res = c_res[l];
    float grid = 2.0f / res;
    int bx = __float2int_rd((px + 1.0f) / grid);
    int by = __float2int_rd((py + 1.0f) / grid);
    int bz = __float2int_rd((pz + 1.0f) / grid);
    float wx = (px - ((float)bx * grid - 1.0f)) / grid;
    float wy = (py - ((float)by * grid - 1.0f)) / grid;
    float wz = (pz - ((float)bz * grid - 1.0f)) / grid;
    const float2* gtbl = emb + (size_t)l * TSIZE;
    unsigned hx0 = (unsigned)bx,       hx1 = (unsigned)(bx + 1);
    unsigned hy0 = (unsigned)by * 2654435761u;
    unsigned hy1 = (unsigned)(by + 1) * 2654435761u;
    unsigned hz0 = (unsigned)bz * 805459861u;
    unsigned hz1 = (unsigned)(bz + 1) * 805459861u;
    float2 e0 = __ldg(gtbl + ((hx0^hy0^hz0) & TMASK));
    float2 e1 = __ldg(gtbl + ((hx0^hy0^hz1) & TMASK));
    float2 e2 = __ldg(gtbl + ((hx0^hy1^hz0) & TMASK));
    float2 e3 = __ldg(gtbl + ((hx0^hy1^hz1) & TMASK));
    float2 e4 = __ldg(gtbl + ((hx1^hy0^hz0) & TMASK));
    float2 e5 = __ldg(gtbl + ((hx1^hy0^hz1) & TMASK));
    float2 e6 = __ldg(gtbl + ((hx1^hy1^hz0) & TMASK));
    float2 e7 = __ldg(gtbl + ((hx1^hy1^hz1) & TMASK));
    float ox = 1.0f-wx, oy = 1.0f-wy, oz = 1.0f-wz;
    float f0 = ox*oy*oz*e0.x, f1 = ox*oy*oz*e0.y;
    f0 = fmaf(ox*oy*wz, e1.x, f0); f1 = fmaf(ox*oy*wz, e1.y, f1);
    f0 = fmaf(ox*wy*oz, e2.x, f0); f1 = fmaf(ox*wy*oz, e2.y, f1);
    f0 = fmaf(ox*wy*wz, e3.x, f0); f1 = fmaf(ox*wy*wz, e3.y, f1);
    f0 = fmaf(wx*oy*oz, e4.x, f0); f1 = fmaf(wx*oy*oz, e4.y, f1);
    f0 = fmaf(wx*oy*wz, e5.x, f0); f1 = fmaf(wx*oy*wz, e5.y, f1);
    f0 = fmaf(wx*wy*oz, e6.x, f0); f1 = fmaf(wx*wy*oz, e6.y, f1);
    f0 = fmaf(wx*wy*wz, e7.x, f0); f1 = fmaf(wx*wy*wz, e7.y, f1);
    out2[tid] = make_float2(f0, f1);
}

extern "C" void kernel_launch(void* const* d_in, const int* in_sizes, int n_in,
                              void* d_out, int out_size)
{
    const float*  x   = (const float*)d_in[0];
    const float2* emb = (const float2*)d_in[1];

    int npts = in_sizes[0] / 3;

    if (npts > MAXPTS) {
        long long total = (long long)npts * NLEV;
        int blocks = (int)((total + 255) / 256);
        k_fallback<<<blocks, 256>>>(x, emb, (float2*)d_out, npts);
        return;
    }

    // 1) spatial counting sort (packed payload)
    k_zero_hist<<<(NBINS + 1023) / 1024, 1024>>>();
    k_key_hist<<<(npts + 255) / 256, 256>>>(x, npts);
    k_scan<<<1, 1024>>>();
    int nh = (npts + 1) / 2;
    k_scatter<<<(nh + 255) / 256, 256>>>(x, npts);

    // 2) coherent main kernel: warp = (32-point group, 4-level chunk)
    int ngroups = (npts + 31) / 32;
    long long nwarps = (long long)ngroups * 4;
    long long nthreads = nwarps * 32;
    int blocks = (int)((nthreads + 255) / 256);
    k_main<<<blocks, 256>>>(emb, (float4*)d_out, npts);
}